// round 14
// baseline (speedup 1.0000x reference)
#include <cuda_runtime.h>
#include <math.h>

// target: (8, 3, 128, 128) = 393216 f32 ; output: (8, 16, 3, 128, 128) = 6291456 f32
// loss = crps_p + 0.1*crps_f ; spectral branch keeps rfft2 bins kh<32, kw<16,
// masked bins contribute 0 but means divide by Gf = 128*65 = 8320.

typedef unsigned long long u64;

#define NIMG_OUT 384
#define NIMG_TGT 24
#define NIMG     408
#define NBINS    512
#define NCRPS_BLK 768     // 393216 pixels / 2 per thread / 256 threads
#define NFREQ_BLK 48      // 12288 (bc,bin) sites / 256

__device__ float    g_acc[4];     // S1, S2p, S1f, S2fp (zero-init; reset by finalize)
__device__ unsigned g_done;
// magnitudes member-contiguous: g_magM[(bc*512 + bin)*16 + m], bc = b*3+c
__device__ float    g_magM[NIMG_TGT * NBINS * 16];
__device__ float    g_magT[NIMG_TGT * NBINS];

// ---------------- compile-time twiddles ----------------
__host__ __device__ constexpr double ccos(double x) {
    double t = 1.0, s = 1.0, x2 = x * x;
    for (int n = 1; n < 16; n++) { t *= -x2 / ((2 * n - 1) * (2 * n)); s += t; }
    return s;
}
__host__ __device__ constexpr double csin(double x) {
    double t = x, s = x, x2 = x * x;
    for (int n = 1; n < 16; n++) { t *= -x2 / ((2 * n) * (2 * n + 1)); s += t; }
    return s;
}
__host__ __device__ constexpr double ang(int j) {
    int m = j & 127;
    int jj = (m <= 64) ? m : m - 128;
    return -2.0 * 3.14159265358979323846 * (double)jj / 128.0;
}
template<int J> __device__ __forceinline__ float TWC() {
    constexpr float v = (float)ccos(ang(J)); return v;
}
template<int J> __device__ __forceinline__ float TWS() {
    constexpr float v = (float)csin(ang(J)); return v;
}

// stage-1: two bins (K0,K1 same parity) over a 64-float half-row, FFMA-imm only
template<int K0, int K1, int W>
__device__ __forceinline__ void s1pair(float x, float* a) {
    a[0] = fmaf(x, TWC<K0 * W>(), a[0]);  a[1] = fmaf(x, TWS<K0 * W>(), a[1]);
    a[2] = fmaf(x, TWC<K1 * W>(), a[2]);  a[3] = fmaf(x, TWS<K1 * W>(), a[3]);
}
template<int K0, int K1, int W4> struct S1R {
    static __device__ __forceinline__ void run(const float* p, float* a) {
        float4 v = *(const float4*)(p + W4 * 4);
        s1pair<K0, K1, 4 * W4 + 0>(v.x, a);
        s1pair<K0, K1, 4 * W4 + 1>(v.y, a);
        s1pair<K0, K1, 4 * W4 + 2>(v.z, a);
        s1pair<K0, K1, 4 * W4 + 3>(v.w, a);
        S1R<K0, K1, W4 + 1>::run(p, a);
    }
};
template<int K0, int K1> struct S1R<K0, K1, 16> {
    static __device__ __forceinline__ void run(const float*, float*) {}
};

// ---------------- packed f32x2 helpers ----------------
__device__ __forceinline__ u64 pack2(float lo, float hi) {
    u64 r; asm("mov.b64 %0, {%1, %2};" : "=l"(r) : "f"(lo), "f"(hi)); return r;
}
__device__ __forceinline__ void unpack2(u64 v, float& lo, float& hi) {
    asm("mov.b64 {%0, %1}, %2;" : "=f"(lo), "=f"(hi) : "l"(v));
}
__device__ __forceinline__ u64 fma2(u64 a, u64 b, u64 c) {
    u64 d; asm("fma.rn.f32x2 %0, %1, %2, %3;" : "=l"(d) : "l"(a), "l"(b), "l"(c)); return d;
}

// ---------------- smem layout for k_dft (52224 B dynamic) ----------------
#define SX_STRIDE 132
#define OFF_SY_F  (2 * 32 * SX_STRIDE)       // 8448
#define OFF_LUT_F (OFF_SY_F + 4352)          // 12800
#define SMEM_BYTES ((OFF_LUT_F + 256) * 4)   // 52224

// Block-reduce + float atomics (RED.F32, pipelined).
__device__ __forceinline__ void reduce_and_add(float s1, float s2, int accIdx) {
    #pragma unroll
    for (int o = 16; o > 0; o >>= 1) {
        s1 += __shfl_down_sync(0xffffffffu, s1, o);
        s2 += __shfl_down_sync(0xffffffffu, s2, o);
    }
    __shared__ float sh1[8], sh2[8];
    int lane = threadIdx.x & 31, wid = threadIdx.x >> 5;
    if (lane == 0) { sh1[wid] = s1; sh2[wid] = s2; }
    __syncthreads();
    if (wid == 0) {
        s1 = (lane < 8) ? sh1[lane] : 0.f;
        s2 = (lane < 8) ? sh2[lane] : 0.f;
        #pragma unroll
        for (int o = 4; o > 0; o >>= 1) {
            s1 += __shfl_down_sync(0xffffffffu, s1, o);
            s2 += __shfl_down_sync(0xffffffffu, s2, o);
        }
        if (lane == 0) {
            atomicAdd(&g_acc[accIdx],     s1);
            atomicAdd(&g_acc[accIdx + 1], s2);
        }
    }
}

// Bitonic sort of 16 register-resident floats (FMNMX on alu pipe).
__device__ __forceinline__ void bitonic16(float* v) {
    #pragma unroll
    for (int k = 2; k <= 16; k <<= 1) {
        #pragma unroll
        for (int j = k >> 1; j > 0; j >>= 1) {
            #pragma unroll
            for (int i = 0; i < 16; i++) {
                int l = i ^ j;
                if (l > i) {
                    float a = v[i], b = v[l];
                    float lo = fminf(a, b), hi = fmaxf(a, b);
                    if ((i & k) == 0) { v[i] = lo; v[l] = hi; }
                    else              { v[i] = hi; v[l] = lo; }
                }
            }
        }
    }
}

// Unordered pairwise |.| sum over 16 sorted values: sum_k (2k-15) * v_(k).
__device__ __forceinline__ float pairsum_sorted(const float* v) {
    float s = 0.f;
    #pragma unroll
    for (int k = 0; k < 16; k++) s = fmaf((float)(2 * k - 15), v[k], s);
    return s;
}

// ---------------- kernel A: pointwise CRPS (independent of DFT; fork stream) ----------
__global__ void __launch_bounds__(256)
k_crps(const float* __restrict__ outp, const float* __restrict__ tgt) {
    const int tid = threadIdx.x;
    int t2 = blockIdx.x * 256 + tid;            // 0..196607
    int b  = t2 / 24576;                        // CG/2 = 24576 float2 per batch
    int r2 = t2 - b * 24576;
    float2 tv = ((const float2*)tgt)[b * 24576 + r2];
    const float2* base = (const float2*)outp + (size_t)b * 393216 + r2;
    float px[16], py[16];
    #pragma unroll
    for (int m = 0; m < 16; m++) {
        float2 p = base[m * 24576];
        px[m] = p.x; py[m] = p.y;
    }
    float s1 = 0.f;
    #pragma unroll
    for (int m = 0; m < 16; m++)
        s1 += fabsf(px[m] - tv.x) + fabsf(py[m] - tv.y);
    bitonic16(px);
    bitonic16(py);
    float s2 = pairsum_sorted(px) + pairsum_sorted(py);
    reduce_and_add(s1, s2, 0);
}

// ---------------- kernel B: pruned low-pass 2D DFT, one block per image ----------------
__global__ void __launch_bounds__(256, 4)
k_dft(const float* __restrict__ outp, const float* __restrict__ tgt) {
    const int tid = threadIdx.x;
    extern __shared__ float smemf[];
    u64*    syu = (u64*)(smemf + OFF_SY_F);
    float2* lut = (float2*)(smemf + OFF_LUT_F);

    const int img = blockIdx.x;
    const float* src;
    float* dstp;
    int dstride;
    if (img < NIMG_OUT) {
        int b = img / 48, rem = img - b * 48;
        int m = rem / 3, c = rem - m * 3;
        src  = outp + (size_t)img * 16384;
        dstp = g_magM + ((b * 3 + c) * NBINS) * 16 + m;   // member-contiguous
        dstride = 16;
    } else {
        int bc = img - NIMG_OUT;
        src  = tgt + (size_t)bc * 16384;
        dstp = g_magT + bc * NBINS;
        dstride = 1;
    }

    if (tid < 128) {
        float s, c;
        sincosf(-6.283185307179586f * (float)tid / 128.0f, &s, &c);
        lut[tid] = make_float2(c, s);
    }

    const int warp = tid >> 5, lane = tid & 31;
    const int wg   = warp >> 2;            // chunk within round
    const int kwb  = (warp & 3) * 4;       // 4 kw bins per warp

    #pragma unroll 1
    for (int round = 0; round < 2; round++) {
        __syncthreads();
        // loader: fold x[w] +/- x[w+64] into s/d halves
        const float4* src4 = (const float4*)src;
        #pragma unroll
        for (int i = 0; i < 4; i++) {
            int e = tid + i * 256;           // 0..1023
            int half = e >> 9, j = e & 511;  // 32 rows x 16 col4-pairs
            int row = j >> 4, c4 = j & 15;
            const float4* rp = src4 + (round * 2 + half) * 1024 + row * 32;
            float4 xa = rp[c4], xb = rp[c4 + 16];
            float* bp = smemf + half * 32 * SX_STRIDE + row * SX_STRIDE;
            *(float4*)(bp + c4 * 4) =
                make_float4(xa.x + xb.x, xa.y + xb.y, xa.z + xb.z, xa.w + xb.w);
            *(float4*)(bp + 64 + c4 * 4) =
                make_float4(xa.x - xb.x, xa.y - xb.y, xa.z - xb.z, xa.w - xb.w);
        }
        __syncthreads();

        const float* myrow = smemf + wg * 32 * SX_STRIDE + lane * SX_STRIDE;
        float aE[4], aO[4];
        #pragma unroll
        for (int i = 0; i < 4; i++) { aE[i] = 0.f; aO[i] = 0.f; }
        // even bins over s-half ; odd bins over d-half
        if      (kwb == 0)  { S1R<0,  2,  0>::run(myrow, aE); S1R<1,  3,  0>::run(myrow + 64, aO); }
        else if (kwb == 4)  { S1R<4,  6,  0>::run(myrow, aE); S1R<5,  7,  0>::run(myrow + 64, aO); }
        else if (kwb == 8)  { S1R<8,  10, 0>::run(myrow, aE); S1R<9,  11, 0>::run(myrow + 64, aO); }
        else                { S1R<12, 14, 0>::run(myrow, aE); S1R<13, 15, 0>::run(myrow + 64, aO); }

        int h = round * 64 + wg * 32 + lane;
        u64* d = syu + h * 17 + kwb;
        d[0] = pack2(aE[0], aE[1]); d[1] = pack2(aO[0], aO[1]);
        d[2] = pack2(aE[2], aE[3]); d[3] = pack2(aO[2], aO[3]);
    }
    __syncthreads();

    // stage 2: thread -> (kw = tid&15, kh in {tid>>4, tid>>4+16}); parity fold h vs h+64
    const int kw  = tid & 15;
    const int kh0 = tid >> 4;
    const int kh1 = kh0 + 16;
    const float sgn = (kh0 & 1) ? -1.f : 1.f;
    const u64 sgn2 = pack2(sgn, sgn);
    u64 U0 = 0, V0 = 0, U1 = 0, V1 = 0;
    #pragma unroll 4
    for (int h = 0; h < 64; h++) {
        u64 ya = syu[h * 17 + kw];
        u64 yb = syu[(h + 64) * 17 + kw];
        u64 y  = fma2(sgn2, yb, ya);
        float yr, yi; unpack2(y, yr, yi);
        u64 yr2 = pack2(yr, yr), yi2 = pack2(yi, yi);
        u64 t0 = *(const u64*)&lut[(kh0 * h) & 127];
        u64 t1 = *(const u64*)&lut[(kh1 * h) & 127];
        U0 = fma2(yr2, t0, U0);
        V0 = fma2(yi2, t0, V0);
        U1 = fma2(yr2, t1, U1);
        V1 = fma2(yi2, t1, V1);
    }
    float u0l, u0h, v0l, v0h, u1l, u1h, v1l, v1h;
    unpack2(U0, u0l, u0h); unpack2(V0, v0l, v0h);
    unpack2(U1, u1l, u1h); unpack2(V1, v1l, v1h);
    float zr0 = u0l - v0h, zi0 = u0h + v0l;
    float zr1 = u1l - v1h, zi1 = u1h + v1l;
    dstp[(kh0 * 16 + kw) * dstride] = sqrtf(zr0 * zr0 + zi0 * zi0);
    dstp[(kh1 * 16 + kw) * dstride] = sqrtf(zr1 * zr1 + zi1 * zi1);
}

// ---------------- kernel C: frequency CRPS + finalize (after join) ----------------
__global__ void __launch_bounds__(256)
k_freq(float* __restrict__ out) {
    const int tid = threadIdx.x;
    int idx = blockIdx.x * 256 + tid;          // (bc, bin) flat, 0..12287
    float t = g_magT[idx];
    const float4* mp = (const float4*)(g_magM + (size_t)idx * 16);
    float4 q0 = mp[0], q1 = mp[1], q2 = mp[2], q3 = mp[3];
    float p[16] = { q0.x, q0.y, q0.z, q0.w, q1.x, q1.y, q1.z, q1.w,
                    q2.x, q2.y, q2.z, q2.w, q3.x, q3.y, q3.z, q3.w };
    float s1 = 0.f;
    #pragma unroll
    for (int m = 0; m < 16; m++) s1 += fabsf(p[m] - t);
    bitonic16(p);
    float s2 = pairsum_sorted(p);
    reduce_and_add(s1, s2, 2);

    __shared__ bool isLast;
    if (tid == 0) {
        __threadfence();
        unsigned prev = atomicAdd(&g_done, 1u);
        isLast = (prev == NFREQ_BLK - 1u);
    }
    __syncthreads();
    if (isLast && tid == 0) {
        __threadfence();
        double S1  = (double)g_acc[0], S2p  = (double)g_acc[1];
        double S1f = (double)g_acc[2], S2fp = (double)g_acc[3];
        const double eps = 0.05 / 16.0;
        const double Np  = 8.0 * 16.0 * 3.0 * 16384.0;
        const double Nf  = 8.0 * 16.0 * 3.0 * 8320.0;
        double crps_p = S1  / Np - (1.0 - eps) * S2p  / (15.0 * Np);
        double crps_f = S1f / Nf - (1.0 - eps) * S2fp / (15.0 * Nf);
        out[0] = (float)(crps_p + 0.1 * crps_f);
        g_acc[0] = 0.f; g_acc[1] = 0.f; g_acc[2] = 0.f; g_acc[3] = 0.f;
        __threadfence();
        g_done = 0u;
    }
}

extern "C" void kernel_launch(void* const* d_in, const int* in_sizes, int n_in,
                              void* d_out, int out_size) {
    const float* target = (const float*)d_in[0];
    const float* output = (const float*)d_in[1];
    if (in_sizes[0] > in_sizes[1]) {
        const float* tmp = target; target = output; output = tmp;
    }
    float* out = (float*)d_out;

    static int inited = 0;
    static cudaStream_t s2;
    static cudaEvent_t evFork, evJoin;
    if (!inited) {   // first call = uncaptured correctness run; resources reused thereafter
        cudaFuncSetAttribute(k_dft, cudaFuncAttributeMaxDynamicSharedMemorySize, SMEM_BYTES);
        cudaStreamCreateWithFlags(&s2, cudaStreamNonBlocking);
        cudaEventCreateWithFlags(&evFork, cudaEventDisableTiming);
        cudaEventCreateWithFlags(&evJoin, cudaEventDisableTiming);
        inited = 1;
    }

    // Fork-join: k_crps (independent of the DFT) runs concurrently on s2.
    cudaEventRecord(evFork, 0);
    cudaStreamWaitEvent(s2, evFork, 0);
    k_crps<<<NCRPS_BLK, 256, 0, s2>>>(output, target);
    k_dft<<<NIMG, 256, SMEM_BYTES, 0>>>(output, target);
    cudaEventRecord(evJoin, s2);
    cudaStreamWaitEvent(0, evJoin, 0);
    k_freq<<<NFREQ_BLK, 256>>>(out);
}

// round 15
// speedup vs baseline: 1.3214x; 1.3214x over previous
#include <cuda_runtime.h>
#include <math.h>

// target: (8, 3, 128, 128) = 393216 f32 ; output: (8, 16, 3, 128, 128) = 6291456 f32
// loss = crps_p + 0.1*crps_f ; spectral branch keeps rfft2 bins kh<32, kw<16,
// masked bins contribute 0 but means divide by Gf = 128*65 = 8320.

typedef unsigned long long u64;

#define NIMG_OUT 384
#define NIMG_TGT 24
#define NIMG     408
#define NBINS    512
#define NCRPS_BLK 768                       // 393216 pixels / 2 per thread / 256 threads
#define NTOT_BLK (NIMG + NCRPS_BLK)         // 1176

__device__ float    g_acc[4];               // S1, S2p, S1f, S2fp (zero-init; reset by finalize)
__device__ unsigned g_done;                 // all-block arrivals  (reset by finalize)
__device__ unsigned g_bc_cnt[NIMG_TGT];     // per-(b,c) DFT completions (reset by finalize)
// magnitudes member-contiguous: g_magM[(bc*512 + bin)*16 + m], bc = b*3+c
__device__ float    g_magM[NIMG_TGT * NBINS * 16];
__device__ float    g_magT[NIMG_TGT * NBINS];

// ---------------- compile-time twiddles ----------------
__host__ __device__ constexpr double ccos(double x) {
    double t = 1.0, s = 1.0, x2 = x * x;
    for (int n = 1; n < 16; n++) { t *= -x2 / ((2 * n - 1) * (2 * n)); s += t; }
    return s;
}
__host__ __device__ constexpr double csin(double x) {
    double t = x, s = x, x2 = x * x;
    for (int n = 1; n < 16; n++) { t *= -x2 / ((2 * n) * (2 * n + 1)); s += t; }
    return s;
}
__host__ __device__ constexpr double ang(int j) {
    int m = j & 127;
    int jj = (m <= 64) ? m : m - 128;
    return -2.0 * 3.14159265358979323846 * (double)jj / 128.0;
}
template<int J> __device__ __forceinline__ float TWC() {
    constexpr float v = (float)ccos(ang(J)); return v;
}
template<int J> __device__ __forceinline__ float TWS() {
    constexpr float v = (float)csin(ang(J)); return v;
}

// stage-1: two bins (K0,K1 same parity) over a 64-float half-row, FFMA-imm only
template<int K0, int K1, int W>
__device__ __forceinline__ void s1pair(float x, float* a) {
    a[0] = fmaf(x, TWC<K0 * W>(), a[0]);  a[1] = fmaf(x, TWS<K0 * W>(), a[1]);
    a[2] = fmaf(x, TWC<K1 * W>(), a[2]);  a[3] = fmaf(x, TWS<K1 * W>(), a[3]);
}
template<int K0, int K1, int W4> struct S1R {
    static __device__ __forceinline__ void run(const float* p, float* a) {
        float4 v = *(const float4*)(p + W4 * 4);
        s1pair<K0, K1, 4 * W4 + 0>(v.x, a);
        s1pair<K0, K1, 4 * W4 + 1>(v.y, a);
        s1pair<K0, K1, 4 * W4 + 2>(v.z, a);
        s1pair<K0, K1, 4 * W4 + 3>(v.w, a);
        S1R<K0, K1, W4 + 1>::run(p, a);
    }
};
template<int K0, int K1> struct S1R<K0, K1, 16> {
    static __device__ __forceinline__ void run(const float*, float*) {}
};

// ---------------- packed f32x2 helpers ----------------
__device__ __forceinline__ u64 pack2(float lo, float hi) {
    u64 r; asm("mov.b64 %0, {%1, %2};" : "=l"(r) : "f"(lo), "f"(hi)); return r;
}
__device__ __forceinline__ void unpack2(u64 v, float& lo, float& hi) {
    asm("mov.b64 {%0, %1}, %2;" : "=f"(lo), "=f"(hi) : "l"(v));
}
__device__ __forceinline__ u64 fma2(u64 a, u64 b, u64 c) {
    u64 d; asm("fma.rn.f32x2 %0, %1, %2, %3;" : "=l"(d) : "l"(a), "l"(b), "l"(c)); return d;
}

// ---------------- smem layout for DFT blocks (52224 B dynamic) ----------------
#define SX_STRIDE 132
#define OFF_SY_F  (2 * 32 * SX_STRIDE)       // 8448
#define OFF_LUT_F (OFF_SY_F + 4352)          // 12800
#define SMEM_BYTES ((OFF_LUT_F + 256) * 4)   // 52224

// Block-reduce + float atomics (RED.F32, pipelined).
__device__ __forceinline__ void reduce_and_add(float s1, float s2, int accIdx) {
    #pragma unroll
    for (int o = 16; o > 0; o >>= 1) {
        s1 += __shfl_down_sync(0xffffffffu, s1, o);
        s2 += __shfl_down_sync(0xffffffffu, s2, o);
    }
    __shared__ float sh1[8], sh2[8];
    int lane = threadIdx.x & 31, wid = threadIdx.x >> 5;
    if (lane == 0) { sh1[wid] = s1; sh2[wid] = s2; }
    __syncthreads();
    if (wid == 0) {
        s1 = (lane < 8) ? sh1[lane] : 0.f;
        s2 = (lane < 8) ? sh2[lane] : 0.f;
        #pragma unroll
        for (int o = 4; o > 0; o >>= 1) {
            s1 += __shfl_down_sync(0xffffffffu, s1, o);
            s2 += __shfl_down_sync(0xffffffffu, s2, o);
        }
        if (lane == 0) {
            atomicAdd(&g_acc[accIdx],     s1);
            atomicAdd(&g_acc[accIdx + 1], s2);
        }
    }
}

// Bitonic sort of 16 register-resident floats (FMNMX on alu pipe).
__device__ __forceinline__ void bitonic16(float* v) {
    #pragma unroll
    for (int k = 2; k <= 16; k <<= 1) {
        #pragma unroll
        for (int j = k >> 1; j > 0; j >>= 1) {
            #pragma unroll
            for (int i = 0; i < 16; i++) {
                int l = i ^ j;
                if (l > i) {
                    float a = v[i], b = v[l];
                    float lo = fminf(a, b), hi = fmaxf(a, b);
                    if ((i & k) == 0) { v[i] = lo; v[l] = hi; }
                    else              { v[i] = hi; v[l] = lo; }
                }
            }
        }
    }
}

// Unordered pairwise |.| sum over 16 sorted values: sum_k (2k-15) * v_(k).
__device__ __forceinline__ float pairsum_sorted(const float* v) {
    float s = 0.f;
    #pragma unroll
    for (int k = 0; k < 16; k++) s = fmaf((float)(2 * k - 15), v[k], s);
    return s;
}

// Single kernel:
//   blocks [0,408)        : pruned low-pass 2D DFT, one image each. The 17th
//                           finisher of each (b,c) group additionally computes
//                           that group's frequency CRPS (inputs guaranteed
//                           complete; no waiting).
//   blocks [408,1176)     : pointwise CRPS (float2 + bitonic).
//   Last of all 1176 blocks (counter) computes the final scalar and resets state.
__global__ void __launch_bounds__(256, 4)
k_main(const float* __restrict__ outp, const float* __restrict__ tgt, float* __restrict__ out) {
    const int tid = threadIdx.x;

    if (blockIdx.x >= NIMG) {
        // ---------------- pointwise CRPS ----------------
        int t2 = (blockIdx.x - NIMG) * 256 + tid;   // 0..196607
        int b  = t2 / 24576;                        // CG/2 = 24576 float2 per batch
        int r2 = t2 - b * 24576;
        float2 tv = ((const float2*)tgt)[b * 24576 + r2];
        const float2* base = (const float2*)outp + (size_t)b * 393216 + r2;
        float px[16], py[16];
        #pragma unroll
        for (int m = 0; m < 16; m++) {
            float2 p = base[m * 24576];
            px[m] = p.x; py[m] = p.y;
        }
        float s1 = 0.f;
        #pragma unroll
        for (int m = 0; m < 16; m++)
            s1 += fabsf(px[m] - tv.x) + fabsf(py[m] - tv.y);
        bitonic16(px);
        bitonic16(py);
        float s2 = pairsum_sorted(px) + pairsum_sorted(py);
        reduce_and_add(s1, s2, 0);
    } else {
        // ---------------- pruned low-pass 2D DFT ----------------
        extern __shared__ float smemf[];
        u64*    syu = (u64*)(smemf + OFF_SY_F);
        float2* lut = (float2*)(smemf + OFF_LUT_F);

        const int img = blockIdx.x;
        const float* src;
        float* dstp;
        int dstride, bc;
        if (img < NIMG_OUT) {
            int b = img / 48, rem = img - b * 48;
            int m = rem / 3, c = rem - m * 3;
            bc   = b * 3 + c;
            src  = outp + (size_t)img * 16384;
            dstp = g_magM + (bc * NBINS) * 16 + m;   // member-contiguous
            dstride = 16;
        } else {
            bc   = img - NIMG_OUT;
            src  = tgt + (size_t)bc * 16384;
            dstp = g_magT + bc * NBINS;
            dstride = 1;
        }

        if (tid < 128) {
            float s, c;
            sincosf(-6.283185307179586f * (float)tid / 128.0f, &s, &c);
            lut[tid] = make_float2(c, s);
        }

        const int warp = tid >> 5, lane = tid & 31;
        const int wg   = warp >> 2;            // chunk within round
        const int kwb  = (warp & 3) * 4;       // 4 kw bins per warp

        #pragma unroll 1
        for (int round = 0; round < 2; round++) {
            __syncthreads();
            // loader: fold x[w] +/- x[w+64] into s/d halves
            const float4* src4 = (const float4*)src;
            #pragma unroll
            for (int i = 0; i < 4; i++) {
                int e = tid + i * 256;           // 0..1023
                int half = e >> 9, j = e & 511;  // 32 rows x 16 col4-pairs
                int row = j >> 4, c4 = j & 15;
                const float4* rp = src4 + (round * 2 + half) * 1024 + row * 32;
                float4 xa = rp[c4], xb = rp[c4 + 16];
                float* bp = smemf + half * 32 * SX_STRIDE + row * SX_STRIDE;
                *(float4*)(bp + c4 * 4) =
                    make_float4(xa.x + xb.x, xa.y + xb.y, xa.z + xb.z, xa.w + xb.w);
                *(float4*)(bp + 64 + c4 * 4) =
                    make_float4(xa.x - xb.x, xa.y - xb.y, xa.z - xb.z, xa.w - xb.w);
            }
            __syncthreads();

            const float* myrow = smemf + wg * 32 * SX_STRIDE + lane * SX_STRIDE;
            float aE[4], aO[4];
            #pragma unroll
            for (int i = 0; i < 4; i++) { aE[i] = 0.f; aO[i] = 0.f; }
            // even bins over s-half ; odd bins over d-half
            if      (kwb == 0)  { S1R<0,  2,  0>::run(myrow, aE); S1R<1,  3,  0>::run(myrow + 64, aO); }
            else if (kwb == 4)  { S1R<4,  6,  0>::run(myrow, aE); S1R<5,  7,  0>::run(myrow + 64, aO); }
            else if (kwb == 8)  { S1R<8,  10, 0>::run(myrow, aE); S1R<9,  11, 0>::run(myrow + 64, aO); }
            else                { S1R<12, 14, 0>::run(myrow, aE); S1R<13, 15, 0>::run(myrow + 64, aO); }

            int h = round * 64 + wg * 32 + lane;
            u64* d = syu + h * 17 + kwb;
            d[0] = pack2(aE[0], aE[1]); d[1] = pack2(aO[0], aO[1]);
            d[2] = pack2(aE[2], aE[3]); d[3] = pack2(aO[2], aO[3]);
        }
        __syncthreads();

        // stage 2: thread -> (kw = tid&15, kh in {tid>>4, tid>>4+16}); parity fold h vs h+64
        const int kw  = tid & 15;
        const int kh0 = tid >> 4;
        const int kh1 = kh0 + 16;
        const float sgn = (kh0 & 1) ? -1.f : 1.f;
        const u64 sgn2 = pack2(sgn, sgn);
        u64 U0 = 0, V0 = 0, U1 = 0, V1 = 0;
        #pragma unroll 4
        for (int h = 0; h < 64; h++) {
            u64 ya = syu[h * 17 + kw];
            u64 yb = syu[(h + 64) * 17 + kw];
            u64 y  = fma2(sgn2, yb, ya);
            float yr, yi; unpack2(y, yr, yi);
            u64 yr2 = pack2(yr, yr), yi2 = pack2(yi, yi);
            u64 t0 = *(const u64*)&lut[(kh0 * h) & 127];
            u64 t1 = *(const u64*)&lut[(kh1 * h) & 127];
            U0 = fma2(yr2, t0, U0);
            V0 = fma2(yi2, t0, V0);
            U1 = fma2(yr2, t1, U1);
            V1 = fma2(yi2, t1, V1);
        }
        float u0l, u0h, v0l, v0h, u1l, u1h, v1l, v1h;
        unpack2(U0, u0l, u0h); unpack2(V0, v0l, v0h);
        unpack2(U1, u1l, u1h); unpack2(V1, v1l, v1h);
        float zr0 = u0l - v0h, zi0 = u0h + v0l;
        float zr1 = u1l - v1h, zi1 = u1h + v1l;
        dstp[(kh0 * 16 + kw) * dstride] = sqrtf(zr0 * zr0 + zi0 * zi0);
        dstp[(kh1 * 16 + kw) * dstride] = sqrtf(zr1 * zr1 + zi1 * zi1);

        // ---- per-(b,c) completion: the 17th finisher computes this bc's freq CRPS ----
        __shared__ bool doFreq;
        __threadfence();               // release this block's magnitude stores
        __syncthreads();               // all threads' stores precede the count
        if (tid == 0) {
            unsigned prev = atomicAdd(&g_bc_cnt[bc], 1u);
            doFreq = (prev == 16u);    // 17th of {16 members + target}
        }
        __syncthreads();
        if (doFreq) {
            if (tid == 0) __threadfence();   // acquire: other blocks' stores now visible
            __syncthreads();
            float s1 = 0.f, s2 = 0.f;
            #pragma unroll
            for (int i = 0; i < 2; i++) {
                int site = bc * NBINS + tid + i * 256;
                float t = g_magT[site];
                const float4* mp = (const float4*)(g_magM + (size_t)site * 16);
                float4 q0 = mp[0], q1 = mp[1], q2 = mp[2], q3 = mp[3];
                float p[16] = { q0.x, q0.y, q0.z, q0.w, q1.x, q1.y, q1.z, q1.w,
                                q2.x, q2.y, q2.z, q2.w, q3.x, q3.y, q3.z, q3.w };
                #pragma unroll
                for (int m = 0; m < 16; m++) s1 += fabsf(p[m] - t);
                bitonic16(p);
                s2 += pairsum_sorted(p);
            }
            reduce_and_add(s1, s2, 2);
        }
    }

    // ---- last of all blocks finalizes (all contributions strictly precede it) ----
    if (tid == 0) {
        __threadfence();
        unsigned prev = atomicAdd(&g_done, 1u);
        if (prev == NTOT_BLK - 1u) {
            __threadfence();
            float S1  = g_acc[0], S2p  = g_acc[1];
            float S1f = g_acc[2], S2fp = g_acc[3];
            const float eps = 0.05f / 16.0f;
            const float Np  = 8.0f * 16.0f * 3.0f * 16384.0f;
            const float Nf  = 8.0f * 16.0f * 3.0f * 8320.0f;
            float crps_p = S1  / Np - (1.0f - eps) * S2p  / (15.0f * Np);
            float crps_f = S1f / Nf - (1.0f - eps) * S2fp / (15.0f * Nf);
            out[0] = crps_p + 0.1f * crps_f;
            g_acc[0] = 0.f; g_acc[1] = 0.f; g_acc[2] = 0.f; g_acc[3] = 0.f;
            #pragma unroll
            for (int i = 0; i < NIMG_TGT; i++) g_bc_cnt[i] = 0u;
            __threadfence();
            g_done = 0u;
        }
    }
}

extern "C" void kernel_launch(void* const* d_in, const int* in_sizes, int n_in,
                              void* d_out, int out_size) {
    const float* target = (const float*)d_in[0];
    const float* output = (const float*)d_in[1];
    if (in_sizes[0] > in_sizes[1]) {
        const float* tmp = target; target = output; output = tmp;
    }
    float* out = (float*)d_out;

    static int smem_set = 0;
    if (!smem_set) {
        cudaFuncSetAttribute(k_main, cudaFuncAttributeMaxDynamicSharedMemorySize, SMEM_BYTES);
        smem_set = 1;
    }

    k_main<<<NTOT_BLK, 256, SMEM_BYTES>>>(output, target, out);
}